// round 13
// baseline (speedup 1.0000x reference)
#include <cuda_runtime.h>
#include <math.h>

#define B_    64
#define N_    20000
#define D_    128
#define F1_   512
#define F2_   256
#define KSEL  20
#define NROWS (B_ * KSEL)            /* 1280 */
#define NSAMP (NROWS * N_)           /* 25,600,000 */

// ---------------- scratch (device globals; no allocation allowed) ----------
__device__ float    g_V[N_ * D_];        // V rows
__device__ float    g_logT[N_ * B_];     // logits transposed [n][b]
__device__ float    g_Q[B_ * D_];
__device__ float    g_qpT[D_ * B_];      // q_part transposed [d][b]
__device__ int      g_maxenc[B_];        // per-b max logit (order-preserving enc)
__device__ int      g_sel[NROWS];        // argmax indices
__device__ unsigned g_mb[NSAMP + 2048];  // 23-bit mantissas (+pad for uint4 overread)

__device__ __forceinline__ int enc_f(float f) {
    int i = __float_as_int(f);
    return i >= 0 ? i : i ^ 0x7fffffff;
}
__device__ __forceinline__ float dec_f(int i) {
    return __int_as_float(i >= 0 ? i : i ^ 0x7fffffff);
}

#define BAR_GEMM() asm volatile("bar.sync 1, 256;" ::: "memory")

__global__ void k_init() {
    if (threadIdx.x < B_) g_maxenc[threadIdx.x] = (int)0x80000000;
}

// ---------------- Kernel A: Q = pe@Wq+bq ; q_part = Q@W1[:D] ----------------
__global__ __launch_bounds__(128) void k_A(
    const float* __restrict__ pe, const float* __restrict__ Wq,
    const float* __restrict__ bq, const float* __restrict__ W1)
{
    __shared__ float pe_s[F1_];
    __shared__ float q_s[D_];
    int b = blockIdx.x, d = threadIdx.x;
    for (int i = d; i < F1_; i += 128) pe_s[i] = pe[b * F1_ + i];
    __syncthreads();
    float acc = 0.f;
#pragma unroll 8
    for (int f = 0; f < F1_; ++f) acc = fmaf(pe_s[f], Wq[f * D_ + d], acc);
    acc += bq[d];
    g_Q[b * D_ + d] = acc;
    q_s[d] = acc;
    __syncthreads();
    float a2 = 0.f;
#pragma unroll 8
    for (int e = 0; e < D_; ++e) a2 = fmaf(q_s[e], W1[e * D_ + d], a2);
    g_qpT[d * B_ + b] = a2;                    // store transposed
}

// ---------------- threefry2x32, key=(0,42), 20 rounds -----------------------
__device__ __forceinline__ void threefry(unsigned c0, unsigned c1,
                                         unsigned& o0, unsigned& o1)
{
    const unsigned k0 = 0u, k1 = 42u, k2 = 0x1BD11BDAu ^ 42u;
    unsigned x0 = c0 + k0, x1 = c1 + k1;
#define TFR(r) { x0 += x1; x1 = __funnelshift_l(x1, x1, (r)); x1 ^= x0; }
    TFR(13) TFR(15) TFR(26) TFR(6)
    x0 += k1; x1 += k2 + 1u;
    TFR(17) TFR(29) TFR(16) TFR(24)
    x0 += k2; x1 += k0 + 2u;
    TFR(13) TFR(15) TFR(26) TFR(6)
    x0 += k0; x1 += k1 + 3u;
    TFR(17) TFR(29) TFR(16) TFR(24)
    x0 += k1; x1 += k2 + 4u;
    TFR(13) TFR(15) TFR(26) TFR(6)
    x0 += k2; x1 += k0 + 5u;
#undef TFR
    o0 = x0; o1 = x1;
}

__device__ __forceinline__ unsigned hash_mb(unsigned c1) {
    unsigned o0, o1;
    threefry(0u, c1, o0, o1);
    return (o0 ^ o1) >> 9;             // 23-bit mantissa of uniform
}

// ======== Fused kernel: 256 GEMM threads + 128 hash threads per block =======
__device__ __forceinline__ void gemm_tile_body(
    int n0, int t, float* sm,
    const float* __restrict__ ge,
    const float* __restrict__ Wk, const float* __restrict__ bk,
    const float* __restrict__ Wv, const float* __restrict__ bv,
    const float* __restrict__ W1, const float* __restrict__ b1,
    const float* __restrict__ w2, const float* __restrict__ b2)
{
    float* ge_s = sm;                  // 8192 (later: qpT [d][b])
    float* km_s = sm + 8192;           // 4096
    float* kp_s = sm + 12288;          // 4096
    float* w2_s = sm + 16384;          // 128

    // phase 1: load 32x256 gene tile
    {
        const float4* src = (const float4*)(ge + (size_t)n0 * F2_);
        float4* dst = (float4*)ge_s;
#pragma unroll
        for (int i = 0; i < 8; ++i) dst[t + i * 256] = src[t + i * 256];
    }
    BAR_GEMM();

    int d = t & 127, gh = t >> 7;      // column d, 16 genes each half

    // phase 2: Km and V
    float accK[16], accV[16];
#pragma unroll
    for (int i = 0; i < 16; ++i) { accK[i] = 0.f; accV[i] = 0.f; }
    const float* gb = ge_s + gh * 16 * F2_;
    for (int f = 0; f < F2_; f += 4) {
        float wk0 = Wk[(f + 0) * D_ + d], wk1 = Wk[(f + 1) * D_ + d];
        float wk2 = Wk[(f + 2) * D_ + d], wk3 = Wk[(f + 3) * D_ + d];
        float wv0 = Wv[(f + 0) * D_ + d], wv1 = Wv[(f + 1) * D_ + d];
        float wv2 = Wv[(f + 2) * D_ + d], wv3 = Wv[(f + 3) * D_ + d];
#pragma unroll
        for (int i = 0; i < 16; ++i) {
            float4 g4 = *(const float4*)(gb + i * F2_ + f);
            accK[i] = fmaf(g4.x, wk0, accK[i]); accK[i] = fmaf(g4.y, wk1, accK[i]);
            accK[i] = fmaf(g4.z, wk2, accK[i]); accK[i] = fmaf(g4.w, wk3, accK[i]);
            accV[i] = fmaf(g4.x, wv0, accV[i]); accV[i] = fmaf(g4.y, wv1, accV[i]);
            accV[i] = fmaf(g4.z, wv2, accV[i]); accV[i] = fmaf(g4.w, wv3, accV[i]);
        }
    }
    {
        float bkd = bk[d], bvd = bv[d];
#pragma unroll
        for (int i = 0; i < 16; ++i) {
            int g = gh * 16 + i;
            km_s[g * D_ + d] = accK[i] + bkd;
            g_V[(size_t)(n0 + g) * D_ + d] = accV[i] + bvd;
        }
    }
    BAR_GEMM();                        // phase2 done reading ge_s

    // overwrite ge_s with qpT [d][b]; load w2
    for (int j = t; j < B_ * D_; j += 256) ge_s[j] = g_qpT[j];
    if (t < D_) w2_s[t] = w2[t];

    // phase 3: k_part (+b1)
    float accP[16];
#pragma unroll
    for (int i = 0; i < 16; ++i) accP[i] = 0.f;
    for (int e = 0; e < D_; e += 4) {
        float w10 = W1[(D_ + e + 0) * D_ + d], w11 = W1[(D_ + e + 1) * D_ + d];
        float w12 = W1[(D_ + e + 2) * D_ + d], w13 = W1[(D_ + e + 3) * D_ + d];
#pragma unroll
        for (int i = 0; i < 16; ++i) {
            float4 k4 = *(const float4*)(km_s + (gh * 16 + i) * D_ + e);
            accP[i] = fmaf(k4.x, w10, accP[i]); accP[i] = fmaf(k4.y, w11, accP[i]);
            accP[i] = fmaf(k4.z, w12, accP[i]); accP[i] = fmaf(k4.w, w13, accP[i]);
        }
    }
    {
        float b1d = b1[d];
#pragma unroll
        for (int i = 0; i < 16; ++i) kp_s[(gh * 16 + i) * D_ + d] = accP[i] + b1d;
    }
    BAR_GEMM();

    // phase 4: sim -> logits  (thread owns batch b, 8 genes)
    int b  = t & 63, gq = t >> 6;
    float acc[8];
#pragma unroll
    for (int i = 0; i < 8; ++i) acc[i] = 0.f;
    const float* kpg = kp_s + gq * 8 * D_;
    const float* qpT = ge_s;           // [d][b]
    for (int dd = 0; dd < D_; ++dd) {
        float qp = qpT[dd * B_ + b];
        float wv = w2_s[dd];
#pragma unroll
        for (int i = 0; i < 8; ++i) {
            float x = qp + kpg[i * D_ + dd];
            float l = fmaxf(x, 0.1f * x);      // leaky_relu(x, 0.1)
            acc[i]  = fmaf(l, wv, acc[i]);
        }
    }
    float b2v = b2[0];
    float lmax = -3.4e38f;
#pragma unroll
    for (int i = 0; i < 8; ++i) {
        float lg = (acc[i] + b2v) * 2.0f;      // /TEMP, TEMP=0.5 exact
        g_logT[(size_t)(n0 + gq * 8 + i) * B_ + b] = lg;
        lmax = fmaxf(lmax, lg);
    }
    atomicMax(&g_maxenc[b], enc_f(lmax));
}

__global__ __launch_bounds__(384, 2) void k_BH(
    const float* __restrict__ ge,
    const float* __restrict__ Wk, const float* __restrict__ bk,
    const float* __restrict__ Wv, const float* __restrict__ bv,
    const float* __restrict__ W1, const float* __restrict__ b1,
    const float* __restrict__ w2, const float* __restrict__ b2)
{
    extern __shared__ float sm[];
    int t = threadIdx.x;
    if (t < 256) {
        gemm_tile_body(blockIdx.x * 32, t, sm, ge, Wk, bk, Wv, bv, W1, b1, w2, b2);
    } else {
        // hash warps: flat counter == flat store index. 2500 warps x 10240.
        int w = (t - 256) >> 5, ln = t & 31;
        unsigned start = (unsigned)(blockIdx.x * 4 + w) * 10240u;
        unsigned end   = start + 10240u;
        for (unsigned i = start + (unsigned)ln; i < end; i += 128u) {
            unsigned m0 = hash_mb(i);
            unsigned m1 = hash_mb(i + 32u);
            unsigned m2 = hash_mb(i + 64u);
            unsigned m3 = hash_mb(i + 96u);
            g_mb[i]      = m0;
            g_mb[i + 32] = m1;
            g_mb[i + 64] = m2;
            g_mb[i + 96] = m3;
        }
    }
}

// ------- k_scan: stream mantissas (uint4 x2), warp-shared conservative prune
__device__ __forceinline__ unsigned mk_mth(float tt) {
    tt -= 1e-3f;
    if (!(tt > -80.f)) return 0u;
    float v = expf(-expf(-tt)) * (1.0f - 1e-6f);
    return (unsigned)(v * 8388608.0f); // floor -> conservative
}

__device__ __forceinline__ void cand(float& x, int& xi,
                                     unsigned mb, int n, int b, unsigned mth) {
    if (mb >= mth) {
        float u = __uint_as_float(mb | 0x3f800000u) - 1.0f;
        if (!(u > 0.f)) u = 1.17549435e-38f;
        float gum = -logf(-logf(u));
        float xc = g_logT[(size_t)n * B_ + b] + gum;
        if (xc > x || (xc == x && n < xi)) { x = xc; xi = n; }
    }
}

__device__ __forceinline__ void warp_update(float& M, int& im, unsigned& mth,
                                            float x, int xi, float Lmax) {
#pragma unroll
    for (int o = 16; o; o >>= 1) {
        float ox = __shfl_xor_sync(0xffffffffu, x, o);
        int   oi = __shfl_xor_sync(0xffffffffu, xi, o);
        if (ox > x || (ox == x && oi < xi)) { x = ox; xi = oi; }
    }
    if (x > M || (x == M && xi < im)) { M = x; im = xi; mth = mk_mth(M - Lmax); }
}

__global__ __launch_bounds__(256) void k_scan() {
    int r = blockIdx.x;                // r = b*KSEL + k, 1280 blocks
    int b = r / KSEL;
    int t = threadIdx.x;
    float Lmax = dec_f(g_maxenc[b]);
    const uint4* mb4 = (const uint4*)(g_mb + (size_t)r * N_);  // 5000 uint4/row

    float    M   = -3.4e38f;
    int      im  = 0;
    unsigned mth = 0u;

    // 10 uniform iterations: q covers 0..5119 via two legs (q, q+256)
    for (int q = t; q < 5120; q += 512) {
        uint4 v0 = mb4[q];             // q <= 4863 < 5000: always valid
        uint4 v1 = mb4[q + 256];       // may overrun row (array padded)
        unsigned mx0 = max(max(v0.x, v0.y), max(v0.z, v0.w));
        unsigned mx1 = max(max(v1.x, v1.y), max(v1.z, v1.w));
        if (__ballot_sync(0xffffffffu, max(mx0, mx1) >= mth)) {
            float x = -3.4e38f; int xi = 0x7fffffff;
            int n0 = q * 4;
            cand(x, xi, v0.x, n0,     b, mth);
            cand(x, xi, v0.y, n0 + 1, b, mth);
            cand(x, xi, v0.z, n0 + 2, b, mth);
            cand(x, xi, v0.w, n0 + 3, b, mth);
            int n1 = (q + 256) * 4;
            if (n1 < N_) {             // whole leg valid or whole leg padding
                cand(x, xi, v1.x, n1,     b, mth);
                cand(x, xi, v1.y, n1 + 1, b, mth);
                cand(x, xi, v1.z, n1 + 2, b, mth);
                cand(x, xi, v1.w, n1 + 3, b, mth);
            }
            warp_update(M, im, mth, x, xi, Lmax);
        }
    }

    // cross-warp reduction (M/im warp-uniform; lane 0 reports)
    __shared__ float sv[8];
    __shared__ int   si[8];
    int wrp = t >> 5, ln = t & 31;
    if (ln == 0) { sv[wrp] = M; si[wrp] = im; }
    __syncthreads();
    if (t == 0) {
        float bm = sv[0]; int bi = si[0];
        for (int w = 1; w < 8; ++w) {
            if (sv[w] > bm || (sv[w] == bm && si[w] < bi)) { bm = sv[w]; bi = si[w]; }
        }
        g_sel[r] = bi;
    }
}

// ---------------- Kernel D: gather V, K-softmax, context --------------------
__global__ __launch_bounds__(128) void k_D(float* __restrict__ out) {
    int b = blockIdx.x, t = threadIdx.x;
    int wrp = t >> 5, ln = t & 31;
    __shared__ int   sidx[KSEL];
    __shared__ float ssc[KSEL];
    __shared__ float sw[KSEL];
    if (t < KSEL) sidx[t] = g_sel[b * KSEL + t];
    __syncthreads();
    const float* qrow = g_Q + b * D_;
    for (int k = wrp; k < KSEL; k += 4) {
        const float* vrow = g_V + (size_t)sidx[k] * D_;
        float s = 0.f;
#pragma unroll
        for (int j = 0; j < 4; ++j) { int dd = ln + 32 * j; s = fmaf(qrow[dd], vrow[dd], s); }
#pragma unroll
        for (int o = 16; o; o >>= 1) s += __shfl_xor_sync(0xffffffffu, s, o);
        if (ln == 0) ssc[k] = s * 0.08838834764831845f;   // 1/sqrt(128)
    }
    __syncthreads();
    if (t == 0) {
        float m = -3.4e38f;
        for (int k = 0; k < KSEL; ++k) m = fmaxf(m, ssc[k]);
        float sum = 0.f;
        for (int k = 0; k < KSEL; ++k) { float e = expf(ssc[k] - m); sw[k] = e; sum += e; }
        float inv = 1.0f / sum;
        for (int k = 0; k < KSEL; ++k) sw[k] *= inv;
    }
    __syncthreads();
    {
        float acc = 0.f;
#pragma unroll 4
        for (int k = 0; k < KSEL; ++k)
            acc = fmaf(sw[k], g_V[(size_t)sidx[k] * D_ + t], acc);
        out[b * D_ + t] = acc;
    }
}

// ---------------- launch -----------------------------------------------------
extern "C" void kernel_launch(void* const* d_in, const int* in_sizes, int n_in,
                              void* d_out, int out_size) {
    const float* pe = (const float*)d_in[0];
    const float* ge = (const float*)d_in[1];
    const float* Wq = (const float*)d_in[2];
    const float* bq = (const float*)d_in[3];
    const float* Wk = (const float*)d_in[4];
    const float* bk = (const float*)d_in[5];
    const float* Wv = (const float*)d_in[6];
    const float* bv = (const float*)d_in[7];
    const float* W1 = (const float*)d_in[8];
    const float* b1 = (const float*)d_in[9];
    const float* w2 = (const float*)d_in[10];
    const float* b2 = (const float*)d_in[11];

    const int SMEM_B = 16512 * sizeof(float);   // 66048 bytes
    cudaFuncSetAttribute(k_BH, cudaFuncAttributeMaxDynamicSharedMemorySize, SMEM_B);

    k_init<<<1, 64>>>();
    k_A<<<B_, 128>>>(pe, Wq, bq, W1);
    k_BH<<<N_ / 32, 384, SMEM_B>>>(ge, Wk, bk, Wv, bv, W1, b1, w2, b2);
    k_scan<<<NROWS, 256>>>();
    k_D<<<B_, 128>>>((float*)d_out);
}

// round 14
// speedup vs baseline: 1.2557x; 1.2557x over previous
#include <cuda_runtime.h>
#include <math.h>

#define B_    64
#define N_    20000
#define D_    128
#define F1_   512
#define F2_   256
#define KSEL  20

// ---------------- scratch (device globals; no allocation allowed) ----------
__device__ float g_V[N_ * D_];        // V rows
__device__ float g_logT[N_ * B_];     // logits transposed [n][b]
__device__ float g_Q[B_ * D_];
__device__ float g_qpT[D_ * B_];      // q_part transposed [d][b]
__device__ int   g_maxenc[B_];        // per-b max logit (order-preserving enc)
__device__ int   g_sel[B_ * KSEL];    // argmax indices

__device__ __forceinline__ int enc_f(float f) {
    int i = __float_as_int(f);
    return i >= 0 ? i : i ^ 0x7fffffff;
}
__device__ __forceinline__ float dec_f(int i) {
    return __int_as_float(i >= 0 ? i : i ^ 0x7fffffff);
}

__global__ void k_init() {
    if (threadIdx.x < B_) g_maxenc[threadIdx.x] = (int)0x80000000;
}

// ---------------- Kernel A: Q = pe@Wq+bq ; q_part = Q@W1[:D] ----------------
__global__ __launch_bounds__(128) void k_A(
    const float* __restrict__ pe, const float* __restrict__ Wq,
    const float* __restrict__ bq, const float* __restrict__ W1)
{
    __shared__ float pe_s[F1_];
    __shared__ float q_s[D_];
    int b = blockIdx.x, d = threadIdx.x;
    for (int i = d; i < F1_; i += 128) pe_s[i] = pe[b * F1_ + i];
    __syncthreads();
    float acc = 0.f;
#pragma unroll 8
    for (int f = 0; f < F1_; ++f) acc = fmaf(pe_s[f], Wq[f * D_ + d], acc);
    acc += bq[d];
    g_Q[b * D_ + d] = acc;
    q_s[d] = acc;
    __syncthreads();
    float a2 = 0.f;
#pragma unroll 8
    for (int e = 0; e < D_; ++e) a2 = fmaf(q_s[e], W1[e * D_ + d], a2);
    g_qpT[d * B_ + b] = a2;                    // store transposed
}

// ---------------- Kernel B: per-gene fused Km/V/k_part/logits (R4) ----------
__global__ __launch_bounds__(256) void k_B(
    const float* __restrict__ ge,
    const float* __restrict__ Wk, const float* __restrict__ bk,
    const float* __restrict__ Wv, const float* __restrict__ bv,
    const float* __restrict__ W1, const float* __restrict__ b1,
    const float* __restrict__ w2, const float* __restrict__ b2)
{
    extern __shared__ float sm[];
    float* ge_s = sm;                  // 8192 (later: qpT [d][b])
    float* km_s = sm + 8192;           // 4096
    float* kp_s = sm + 12288;          // 4096
    float* w2_s = sm + 16384;          // 128

    int t  = threadIdx.x;
    int n0 = blockIdx.x * 32;

    // phase 1: load 32x256 gene tile
    {
        const float4* src = (const float4*)(ge + (size_t)n0 * F2_);
        float4* dst = (float4*)ge_s;
#pragma unroll
        for (int i = 0; i < 8; ++i) dst[t + i * 256] = src[t + i * 256];
    }
    __syncthreads();

    int d = t & 127, gh = t >> 7;      // column d, 16 genes each half

    // phase 2: Km and V
    float accK[16], accV[16];
#pragma unroll
    for (int i = 0; i < 16; ++i) { accK[i] = 0.f; accV[i] = 0.f; }
    const float* gb = ge_s + gh * 16 * F2_;
    for (int f = 0; f < F2_; f += 4) {
        float wk0 = Wk[(f + 0) * D_ + d], wk1 = Wk[(f + 1) * D_ + d];
        float wk2 = Wk[(f + 2) * D_ + d], wk3 = Wk[(f + 3) * D_ + d];
        float wv0 = Wv[(f + 0) * D_ + d], wv1 = Wv[(f + 1) * D_ + d];
        float wv2 = Wv[(f + 2) * D_ + d], wv3 = Wv[(f + 3) * D_ + d];
#pragma unroll
        for (int i = 0; i < 16; ++i) {
            float4 g4 = *(const float4*)(gb + i * F2_ + f);
            accK[i] = fmaf(g4.x, wk0, accK[i]); accK[i] = fmaf(g4.y, wk1, accK[i]);
            accK[i] = fmaf(g4.z, wk2, accK[i]); accK[i] = fmaf(g4.w, wk3, accK[i]);
            accV[i] = fmaf(g4.x, wv0, accV[i]); accV[i] = fmaf(g4.y, wv1, accV[i]);
            accV[i] = fmaf(g4.z, wv2, accV[i]); accV[i] = fmaf(g4.w, wv3, accV[i]);
        }
    }
    {
        float bkd = bk[d], bvd = bv[d];
#pragma unroll
        for (int i = 0; i < 16; ++i) {
            int g = gh * 16 + i;
            km_s[g * D_ + d] = accK[i] + bkd;
            g_V[(size_t)(n0 + g) * D_ + d] = accV[i] + bvd;
        }
    }
    __syncthreads();                   // phase2 done reading ge_s

    // overwrite ge_s with qpT [d][b]; load w2
    for (int j = t; j < B_ * D_; j += 256) ge_s[j] = g_qpT[j];
    if (t < D_) w2_s[t] = w2[t];

    // phase 3: k_part (+b1)
    float accP[16];
#pragma unroll
    for (int i = 0; i < 16; ++i) accP[i] = 0.f;
    for (int e = 0; e < D_; e += 4) {
        float w10 = W1[(D_ + e + 0) * D_ + d], w11 = W1[(D_ + e + 1) * D_ + d];
        float w12 = W1[(D_ + e + 2) * D_ + d], w13 = W1[(D_ + e + 3) * D_ + d];
#pragma unroll
        for (int i = 0; i < 16; ++i) {
            float4 k4 = *(const float4*)(km_s + (gh * 16 + i) * D_ + e);
            accP[i] = fmaf(k4.x, w10, accP[i]); accP[i] = fmaf(k4.y, w11, accP[i]);
            accP[i] = fmaf(k4.z, w12, accP[i]); accP[i] = fmaf(k4.w, w13, accP[i]);
        }
    }
    {
        float b1d = b1[d];
#pragma unroll
        for (int i = 0; i < 16; ++i) kp_s[(gh * 16 + i) * D_ + d] = accP[i] + b1d;
    }
    __syncthreads();

    // phase 4: sim -> logits  (thread owns batch b, 8 genes)
    int b  = t & 63, gq = t >> 6;
    float acc[8];
#pragma unroll
    for (int i = 0; i < 8; ++i) acc[i] = 0.f;
    const float* kpg = kp_s + gq * 8 * D_;
    const float* qpT = ge_s;           // [d][b]
    for (int dd = 0; dd < D_; ++dd) {
        float qp = qpT[dd * B_ + b];
        float wv = w2_s[dd];
#pragma unroll
        for (int i = 0; i < 8; ++i) {
            float x = qp + kpg[i * D_ + dd];
            float l = fmaxf(x, 0.1f * x);      // leaky_relu(x, 0.1)
            acc[i]  = fmaf(l, wv, acc[i]);
        }
    }
    float b2v = b2[0];
    float lmax = -3.4e38f;
#pragma unroll
    for (int i = 0; i < 8; ++i) {
        float lg = (acc[i] + b2v) * 2.0f;      // /TEMP, TEMP=0.5 exact
        g_logT[(size_t)(n0 + gq * 8 + i) * B_ + b] = lg;
        lmax = fmaxf(lmax, lg);
    }
    atomicMax(&g_maxenc[b], enc_f(lmax));
}

// ------- Kernel C: threefry gumbel argmax, warp-shared prune, unroll-8 ------
__device__ __forceinline__ void threefry(unsigned c0, unsigned c1,
                                         unsigned& o0, unsigned& o1)
{
    const unsigned k0 = 0u, k1 = 42u, k2 = 0x1BD11BDAu ^ 42u;
    unsigned x0 = c0 + k0, x1 = c1 + k1;
#define TFR(r) { x0 += x1; x1 = __funnelshift_l(x1, x1, (r)); x1 ^= x0; }
    TFR(13) TFR(15) TFR(26) TFR(6)
    x0 += k1; x1 += k2 + 1u;
    TFR(17) TFR(29) TFR(16) TFR(24)
    x0 += k2; x1 += k0 + 2u;
    TFR(13) TFR(15) TFR(26) TFR(6)
    x0 += k0; x1 += k1 + 3u;
    TFR(17) TFR(29) TFR(16) TFR(24)
    x0 += k1; x1 += k2 + 4u;
    TFR(13) TFR(15) TFR(26) TFR(6)
    x0 += k2; x1 += k0 + 5u;
#undef TFR
    o0 = x0; o1 = x1;
}

__device__ __forceinline__ unsigned hash_mb(unsigned c1) {
    unsigned o0, o1;
    threefry(0u, c1, o0, o1);
    return (o0 ^ o1) >> 9;             // 23-bit mantissa of uniform
}

// conservative integer threshold image of (M - Lmax - 1e-3) in u-space
__device__ __forceinline__ unsigned mk_mth(float tt) {
    tt -= 1e-3f;
    if (!(tt > -80.f)) return 0u;
    float v = expf(-expf(-tt)) * (1.0f - 1e-6f);
    return (unsigned)(v * 8388608.0f); // floor -> conservative
}

// evaluate one candidate (bit-identical float path to R4/R12)
__device__ __forceinline__ void cand(float& x, int& xi,
                                     unsigned mb, int n, int b, unsigned mth) {
    if (mb >= mth) {
        float u = __uint_as_float(mb | 0x3f800000u) - 1.0f;
        if (!(u > 0.f)) u = 1.17549435e-38f;
        float gum = -logf(-logf(u));
        float xc = g_logT[(size_t)n * B_ + b] + gum;
        if (xc > x || (xc == x && n < xi)) { x = xc; xi = n; }
    }
}

__device__ __forceinline__ void warp_update(float& M, int& im, unsigned& mth,
                                            float x, int xi, float Lmax) {
#pragma unroll
    for (int o = 16; o; o >>= 1) {
        float ox = __shfl_xor_sync(0xffffffffu, x, o);
        int   oi = __shfl_xor_sync(0xffffffffu, xi, o);
        if (ox > x || (ox == x && oi < xi)) { x = ox; xi = oi; }
    }
    if (x > M || (x == M && xi < im)) { M = x; im = xi; mth = mk_mth(M - Lmax); }
}

__global__ __launch_bounds__(256) void k_C() {
    int r = blockIdx.x;                // r = b*KSEL + k, 1280 blocks
    int b = r / KSEL;
    int t = threadIdx.x;
    unsigned base = (unsigned)r * (unsigned)N_;
    float Lmax = dec_f(g_maxenc[b]);

    // warp-uniform running state
    float    M   = -3.4e38f;
    int      im  = 0;
    unsigned mth = 0u;

    int n = t;
    // 9 uniform groups of 8 samples/lane (covers n in [0, 18432))
    for (; n + 1792 < N_; n += 2048) {
        unsigned m0 = hash_mb(base + (unsigned)n);
        unsigned m1 = hash_mb(base + (unsigned)(n + 256));
        unsigned m2 = hash_mb(base + (unsigned)(n + 512));
        unsigned m3 = hash_mb(base + (unsigned)(n + 768));
        unsigned m4 = hash_mb(base + (unsigned)(n + 1024));
        unsigned m5 = hash_mb(base + (unsigned)(n + 1280));
        unsigned m6 = hash_mb(base + (unsigned)(n + 1536));
        unsigned m7 = hash_mb(base + (unsigned)(n + 1792));
        unsigned mx = max(max(max(m0, m1), max(m2, m3)),
                          max(max(m4, m5), max(m6, m7)));
        if (__ballot_sync(0xffffffffu, mx >= mth)) {   // rare after warm-up
            float x = -3.4e38f; int xi = 0x7fffffff;
            cand(x, xi, m0, n,        b, mth);
            cand(x, xi, m1, n + 256,  b, mth);
            cand(x, xi, m2, n + 512,  b, mth);
            cand(x, xi, m3, n + 768,  b, mth);
            cand(x, xi, m4, n + 1024, b, mth);
            cand(x, xi, m5, n + 1280, b, mth);
            cand(x, xi, m6, n + 1536, b, mth);
            cand(x, xi, m7, n + 1792, b, mth);
            warp_update(M, im, mth, x, xi, Lmax);
        }
    }
    // remainder: 6 full warp-uniform legs + 1 warp0-only leg (all ballot-safe)
    for (; n < N_; n += 256) {
        unsigned m0 = hash_mb(base + (unsigned)n);
        if (__ballot_sync(0xffffffffu, m0 >= mth)) {
            float x = -3.4e38f; int xi = 0x7fffffff;
            cand(x, xi, m0, n, b, mth);
            warp_update(M, im, mth, x, xi, Lmax);
        }
    }

    // cross-warp reduction (M/im warp-uniform; lane 0 reports)
    __shared__ float sv[8];
    __shared__ int   si[8];
    int wrp = t >> 5, ln = t & 31;
    if (ln == 0) { sv[wrp] = M; si[wrp] = im; }
    __syncthreads();
    if (t == 0) {
        float bm = sv[0]; int bi = si[0];
        for (int w = 1; w < 8; ++w) {
            if (sv[w] > bm || (sv[w] == bm && si[w] < bi)) { bm = sv[w]; bi = si[w]; }
        }
        g_sel[r] = bi;
    }
}

// ---------------- Kernel D: gather V, K-softmax, context --------------------
__global__ __launch_bounds__(128) void k_D(float* __restrict__ out) {
    int b = blockIdx.x, t = threadIdx.x;
    int wrp = t >> 5, ln = t & 31;
    __shared__ int   sidx[KSEL];
    __shared__ float ssc[KSEL];
    __shared__ float sw[KSEL];
    if (t < KSEL) sidx[t] = g_sel[b * KSEL + t];
    __syncthreads();
    const float* qrow = g_Q + b * D_;
    for (int k = wrp; k < KSEL; k += 4) {
        const float* vrow = g_V + (size_t)sidx[k] * D_;
        float s = 0.f;
#pragma unroll
        for (int j = 0; j < 4; ++j) { int dd = ln + 32 * j; s = fmaf(qrow[dd], vrow[dd], s); }
#pragma unroll
        for (int o = 16; o; o >>= 1) s += __shfl_xor_sync(0xffffffffu, s, o);
        if (ln == 0) ssc[k] = s * 0.08838834764831845f;   // 1/sqrt(128)
    }
    __syncthreads();
    if (t == 0) {
        float m = -3.4e38f;
        for (int k = 0; k < KSEL; ++k) m = fmaxf(m, ssc[k]);
        float sum = 0.f;
        for (int k = 0; k < KSEL; ++k) { float e = expf(ssc[k] - m); sw[k] = e; sum += e; }
        float inv = 1.0f / sum;
        for (int k = 0; k < KSEL; ++k) sw[k] *= inv;
    }
    __syncthreads();
    {
        float acc = 0.f;
#pragma unroll 4
        for (int k = 0; k < KSEL; ++k)
            acc = fmaf(sw[k], g_V[(size_t)sidx[k] * D_ + t], acc);
        out[b * D_ + t] = acc;
    }
}

// ---------------- launch -----------------------------------------------------
extern "C" void kernel_launch(void* const* d_in, const int* in_sizes, int n_in,
                              void* d_out, int out_size) {
    const float* pe = (const float*)d_in[0];
    const float* ge = (const float*)d_in[1];
    const float* Wq = (const float*)d_in[2];
    const float* bq = (const float*)d_in[3];
    const float* Wk = (const float*)d_in[4];
    const float* bk = (const float*)d_in[5];
    const float* Wv = (const float*)d_in[6];
    const float* bv = (const float*)d_in[7];
    const float* W1 = (const float*)d_in[8];
    const float* b1 = (const float*)d_in[9];
    const float* w2 = (const float*)d_in[10];
    const float* b2 = (const float*)d_in[11];

    const int SMEM_B = 16512 * sizeof(float);   // 66048 bytes
    cudaFuncSetAttribute(k_B, cudaFuncAttributeMaxDynamicSharedMemorySize, SMEM_B);

    k_init<<<1, 64>>>();
    k_A<<<B_, 128>>>(pe, Wq, bq, W1);
    k_B<<<N_ / 32, 256, SMEM_B>>>(ge, Wk, bk, Wv, bv, W1, b1, w2, b2);
    k_C<<<B_ * KSEL, 256>>>();
    k_D<<<B_, 128>>>((float*)d_out);
}